// round 10
// baseline (speedup 1.0000x reference)
#include <cuda_runtime.h>
#include <cuda_bf16.h>

#define BB 256
#define TT 512
#define DD 64
#define HH 128
#define NBLK 256

// ---------------- device scratch (static, no allocation) ----------------
__device__ __nv_bfloat16 g_w1p[32 * 512 * 8];   // [kk][s][u], k = kk*8+u in [0,256)
__device__ __nv_bfloat16 g_wzp[24 * 512 * 8];   // [kk][j][u], k' in [0,192): 0..63 Wih, 64..191 Whh
__device__ unsigned g_bar_count = 0;
__device__ unsigned g_bar_flag = 0;

// ---------------- helpers ----------------
typedef unsigned long long ull;

__device__ __forceinline__ float tanh_fast(float x) {
    float y;
    asm("tanh.approx.f32 %0, %1;" : "=f"(y) : "f"(x));
    return y;
}
__device__ __forceinline__ float sigf(float x) { return 1.f / (1.f + __expf(-x)); }
__device__ __forceinline__ float tanh_ex(float x) {
    x = fminf(fmaxf(x, -15.f), 15.f);
    float e = __expf(2.f * x);
    return (e - 1.f) / (e + 1.f);
}
__device__ __forceinline__ float bl(unsigned u) { return __uint_as_float(u << 16); }
__device__ __forceinline__ float braw(unsigned u) { return __uint_as_float(u); }
__device__ __forceinline__ void ffma2(ull& acc, ull ab, ull cd) {
    asm("fma.rn.f32x2 %0, %1, %2, %0;" : "+l"(acc) : "l"(ab), "l"(cd));
}
// pair {even = u<<16, odd = u raw (tail-compensated)}
__device__ __forceinline__ ull bfpair(unsigned u) {
    ull p;
    asm("{\n\t.reg .b32 lo;\n\t"
        "shl.b32 lo, %1, 16;\n\t"
        "mov.b64 %0, {lo, %1};\n\t}" : "=l"(p) : "r"(u));
    return p;
}
__device__ __forceinline__ ull mk_pair(float lo, float hi) {
    ull p;
    asm("mov.b64 %0, {%1, %2};" : "=l"(p) : "f"(lo), "f"(hi));
    return p;
}
__device__ __forceinline__ float pair_lo(ull p) { return __uint_as_float((unsigned)p); }
__device__ __forceinline__ float pair_hi(ull p) { return __uint_as_float((unsigned)(p >> 32)); }
__device__ __forceinline__ float pair_sum(ull p) { return pair_lo(p) + pair_hi(p); }

// Tail-compensated pair pack: low16 = bf16(we); top16 chosen so the f32
// [top16:low16] best approximates wo. Raw reuse of the odd element carries
// no extra quantization error vs plain bf16.
__device__ __forceinline__ unsigned pack_comp(float we, float wo) {
    __nv_bfloat16 be = __float2bfloat16(we);
    unsigned below = (unsigned)*(unsigned short*)&be;
    unsigned fo = __float_as_uint(wo);
    unsigned c0 = (fo & 0xffff0000u) | below;
    unsigned cm = c0 - 0x10000u;
    unsigned cp = c0 + 0x10000u;
    float d0 = fabsf(__uint_as_float(c0) - wo);
    float dm = fabsf(__uint_as_float(cm) - wo);
    float dp = fabsf(__uint_as_float(cp) - wo);
    unsigned best = c0;
    float bd = d0;
    if (dm < bd) { best = cm; bd = dm; }
    if (dp < bd) { best = cp; }
    return best;
}

// ---------------- smem layout (per block: ONE batch) ----------------
#define S2STRIDE 552
#define SM_S2_BYTES (64 * S2STRIDE * 2)          // 70656
#define SM_SCRATCH  37120                        // stage2 staging; later scan floats (12KB)
#define SM_TOTAL (SM_S2_BYTES + SM_SCRATCH)      // 107776 -> 2 blocks/SM

// ---------------- the one kernel ----------------
__global__ void __launch_bounds__(512, 2) fused_kernel(
    const float* __restrict__ din, const float* __restrict__ Wih,
    const float* __restrict__ Whh, const float* __restrict__ bih,
    const float* __restrict__ bhh, const float* __restrict__ W1,
    const float* __restrict__ b1, const float* __restrict__ W2,
    const float* __restrict__ b2, const float* __restrict__ W3,
    const float* __restrict__ b3, float* __restrict__ out) {
    extern __shared__ char smraw[];
    __nv_bfloat16* s2s = (__nv_bfloat16*)smraw;              // [64][552]
    float* fl   = (float*)(smraw + SM_S2_BYTES);             // scan floats region
    float* hc   = fl;                                         // [256]: h then c
    float* s1s  = hc + 256;                                   // [512]
    float* zhs  = s1s + 512;                                  // [512]
    float* xs   = zhs + 512;                                  // [64]
    float* es   = xs + 64;                                    // [64]
    float* w3s  = es + 64;                                    // [512]
    float* b1s  = w3s + 512;                                  // [512]
    float* bzs  = b1s + 512;                                  // [512]
    float* dinb = bzs + 512;                                  // [64]

    const int tid = threadIdx.x;
    const int b = blockIdx.x;   // one batch per block

    // ======== STAGE 1: pack weights (grid-strided, pair-compensated) ========
    {
        int gidx = blockIdx.x * 512 + tid;
        int gstride = NBLK * 512;
        unsigned* w1d = (unsigned*)g_w1p;
        for (int i = gidx; i < 32 * 512 * 4; i += gstride) {
            int uu2 = (i & 3) * 2, s = (i >> 2) & 511, kk = i >> 11;
            int k0 = kk * 8 + uu2;
            w1d[i] = pack_comp(W1[s * 256 + k0], W1[s * 256 + k0 + 1]);
        }
        unsigned* wzd = (unsigned*)g_wzp;
        for (int i = gidx; i < 24 * 512 * 4; i += gstride) {
            int uu2 = (i & 3) * 2, j = (i >> 2) & 511, kk = i >> 11;
            int k0 = kk * 8 + uu2;
            float v0 = (k0 < 64) ? Wih[j * 64 + k0] : Whh[j * 128 + (k0 - 64)];
            float v1 = (k0 + 1 < 64) ? Wih[j * 64 + k0 + 1] : Whh[j * 128 + (k0 + 1 - 64)];
            wzd[i] = pack_comp(v0, v1);
        }
    }
    // grid barrier (256 blocks, all resident: 2/SM on 148 SMs)
    __syncthreads();
    if (tid == 0) {
        unsigned f0 = *((volatile unsigned*)&g_bar_flag);
        __threadfence();
        unsigned old = atomicAdd(&g_bar_count, 1);
        if (old == NBLK - 1) {
            g_bar_count = 0;
            __threadfence();
            atomicAdd(&g_bar_flag, 1);
        } else {
            while (*((volatile unsigned*)&g_bar_flag) == f0) { __nanosleep(64); }
        }
        __threadfence();
    }
    __syncthreads();

    // ======== STAGE 2: s2[d][s] = sum_t din[b,t,d]*W2[s,t] + b2[s] into SMEM ========
    // Two s-half passes (16 s per thread each) to stay within 64 regs.
    {
        float* w2st  = (float*)(smraw + SM_S2_BYTES);  // [16][516]
        float* dinst = w2st + 16 * 516;                 // [16][64]
        const int lane = tid & 31, sgrp = tid >> 5;     // warp == sgrp
        const int d0 = lane * 2;

        for (int sh = 0; sh < 2; sh++) {
            const int sbase = sgrp * 32 + sh * 16;
            ull acc[2][8];
#pragma unroll
            for (int p = 0; p < 8; p++) {
                float2 bp = *(const float2*)(b2 + sbase + 2 * p);
                acc[0][p] = mk_pair(bp.x, bp.y);
                acc[1][p] = acc[0][p];
            }
            for (int tc = 0; tc < 32; tc++) {
                const int t0 = tc * 16;
                __syncthreads();
                for (int i = tid; i < 16 * 512; i += 512) {
                    int tt = i & 15, sl = i >> 4;
                    w2st[tt * 516 + sl] = W2[(size_t)sl * TT + t0 + tt];
                }
                for (int i = tid; i < 16 * 64; i += 512) {
                    int tt = i >> 6, dd = i & 63;
                    dinst[tt * 64 + dd] = din[((size_t)b * TT + t0 + tt) * DD + dd];
                }
                __syncthreads();
#pragma unroll 4
                for (int tt = 0; tt < 16; tt++) {
                    float2 av = *(const float2*)&dinst[tt * 64 + d0];
                    ull ax = mk_pair(av.x, av.x);
                    ull ay = mk_pair(av.y, av.y);
                    const ull* wrow = (const ull*)(w2st + tt * 516 + sbase);
#pragma unroll
                    for (int p = 0; p < 8; p++) {
                        ull wp = wrow[p];
                        ffma2(acc[0][p], wp, ax);
                        ffma2(acc[1][p], wp, ay);
                    }
                }
            }
#pragma unroll
            for (int dl = 0; dl < 2; dl++) {
                unsigned* row = (unsigned*)(s2s + (size_t)(d0 + dl) * S2STRIDE + sbase);
#pragma unroll
                for (int p = 0; p < 8; p++)
                    row[p] = pack_comp(pair_lo(acc[dl][p]), pair_hi(acc[dl][p]));
            }
            __syncthreads();
        }
    }

    // ======== STAGE 3: init scan constants (scratch region reused) ========
    w3s[tid] = W3[tid];
    b1s[tid] = b1[tid];
    bzs[tid] = bih[tid] + bhh[tid];
    if (tid < 256) hc[tid] = 0.f;
    __syncthreads();
    const float b3v = b3[0];

    // ======== STAGE 4: the scan ========
    for (int t = 0; t < TT; t++) {
        // prefetch din[b, t, .] (hidden behind phase A)
        float dval = 0.f;
        if (tid < 64) dval = din[((size_t)b * TT + t) * DD + tid];

        // ---- Phase A: s1 = [h;c].W1col + b1 ; zh = h.WhhCol + bz ----
        {
            const int s = tid;
            const uint4* w1p = (const uint4*)g_w1p;
            const uint4* whp = (const uint4*)g_wzp + 8 * 512;
            const ulonglong2* h0 = (const ulonglong2*)hc;
            ull aW = 0, aH = 0;
#pragma unroll 4
            for (int kk = 0; kk < 16; kk++) {
                uint4 w = w1p[kk * 512 + s];
                uint4 v = whp[kk * 512 + s];
                ulonglong2 pa = h0[kk * 2], pb = h0[kk * 2 + 1];
                ull w01 = bfpair(w.x), w23 = bfpair(w.y);
                ull w45 = bfpair(w.z), w67 = bfpair(w.w);
                ull v01 = bfpair(v.x), v23 = bfpair(v.y);
                ull v45 = bfpair(v.z), v67 = bfpair(v.w);
                ffma2(aW, w01, pa.x); ffma2(aW, w23, pa.y);
                ffma2(aW, w45, pb.x); ffma2(aW, w67, pb.y);
                ffma2(aH, v01, pa.x); ffma2(aH, v23, pa.y);
                ffma2(aH, v45, pb.x); ffma2(aH, v67, pb.y);
            }
#pragma unroll 4
            for (int kk = 16; kk < 32; kk++) {
                uint4 w = w1p[kk * 512 + s];
                ulonglong2 pa = h0[kk * 2], pb = h0[kk * 2 + 1];
                ull w01 = bfpair(w.x), w23 = bfpair(w.y);
                ull w45 = bfpair(w.z), w67 = bfpair(w.w);
                ffma2(aW, w01, pa.x); ffma2(aW, w23, pa.y);
                ffma2(aW, w45, pb.x); ffma2(aW, w67, pb.y);
            }
            s1s[s] = pair_sum(aW) + b1s[s];
            zhs[s] = pair_sum(aH) + bzs[s];
        }
        if (tid < 64) dinb[tid] = dval;
        __syncthreads();

        // ---- Phase B: e[d] = sum_s tanh(s1+s2)*w3 + b3 (16 subs x 2 rows) ----
        {
            const int sub = tid & 15, grp = tid >> 4;   // grp 0..31
            const int d0 = grp * 2;
            const __nv_bfloat16* rowbase = s2s + (size_t)d0 * S2STRIDE;
            const uint4* r0 = (const uint4*)(rowbase);
            const uint4* r1 = (const uint4*)(rowbase + S2STRIDE);
            const float4* s1f = (const float4*)s1s;
            const float4* w3f = (const float4*)w3s;
            float a0 = 0.f, a1 = 0.f;
#pragma unroll
            for (int i = 0; i < 4; i++) {
                const int q = sub + 16 * i;
                float4 sA = s1f[2 * q], sB = s1f[2 * q + 1];
                float4 wA = w3f[2 * q], wB = w3f[2 * q + 1];
                uint4 v0 = r0[q], v1 = r1[q];
                a0 = fmaf(tanh_fast(sA.x + bl(v0.x)), wA.x, a0);
                a0 = fmaf(tanh_fast(sA.y + braw(v0.x)), wA.y, a0);
                a0 = fmaf(tanh_fast(sA.z + bl(v0.y)), wA.z, a0);
                a0 = fmaf(tanh_fast(sA.w + braw(v0.y)), wA.w, a0);
                a0 = fmaf(tanh_fast(sB.x + bl(v0.z)), wB.x, a0);
                a0 = fmaf(tanh_fast(sB.y + braw(v0.z)), wB.y, a0);
                a0 = fmaf(tanh_fast(sB.z + bl(v0.w)), wB.z, a0);
                a0 = fmaf(tanh_fast(sB.w + braw(v0.w)), wB.w, a0);
                a1 = fmaf(tanh_fast(sA.x + bl(v1.x)), wA.x, a1);
                a1 = fmaf(tanh_fast(sA.y + braw(v1.x)), wA.y, a1);
                a1 = fmaf(tanh_fast(sA.z + bl(v1.y)), wA.z, a1);
                a1 = fmaf(tanh_fast(sA.w + braw(v1.y)), wA.w, a1);
                a1 = fmaf(tanh_fast(sB.x + bl(v1.z)), wB.x, a1);
                a1 = fmaf(tanh_fast(sB.y + braw(v1.z)), wB.y, a1);
                a1 = fmaf(tanh_fast(sB.z + bl(v1.w)), wB.z, a1);
                a1 = fmaf(tanh_fast(sB.w + braw(v1.w)), wB.w, a1);
            }
#pragma unroll
            for (int o = 1; o < 16; o <<= 1) {
                a0 += __shfl_xor_sync(0xffffffffu, a0, o);
                a1 += __shfl_xor_sync(0xffffffffu, a1, o);
            }
            if (sub == 0) {
                es[d0] = a0 + b3v;
                es[d0 + 1] = a1 + b3v;
            }
        }
        __syncthreads();

        // ---- Phase C: softmax over d (no max-subtract: |e| bounded), x = a*x_t ----
        if (tid < 32) {
            float e0 = es[tid], e1 = es[tid + 32];
            float p0 = __expf(e0), p1 = __expf(e1);
            float sm = p0 + p1;
#pragma unroll
            for (int o = 16; o; o >>= 1) sm += __shfl_xor_sync(0xffffffffu, sm, o);
            float inv = 1.f / sm;
            xs[tid]      = p0 * inv * dinb[tid];
            xs[tid + 32] = p1 * inv * dinb[tid + 32];
        }
        __syncthreads();

        // ---- Phase D: z[j] = x.WihCol + zh[j] (Wih from L2) ----
        {
            const int j = tid;
            const uint4* wip = (const uint4*)g_wzp;   // kk 0..7 = Wih
            const ulonglong2* xv = (const ulonglong2*)xs;
            ull a = 0;
#pragma unroll
            for (int kk = 0; kk < 8; kk++) {
                uint4 w = wip[kk * 512 + j];
                ulonglong2 xa = xv[kk * 2], xb = xv[kk * 2 + 1];
                ffma2(a, bfpair(w.x), xa.x); ffma2(a, bfpair(w.y), xa.y);
                ffma2(a, bfpair(w.z), xb.x); ffma2(a, bfpair(w.w), xb.y);
            }
            zhs[j] += pair_sum(a);
        }
        __syncthreads();

        // ---- Phase E: gates, state update, output ----
        if (tid < 128) {
            const int m = tid;
            float iv = zhs[m];
            float fv = zhs[128 + m];
            float gv = zhs[256 + m];
            float ov = zhs[384 + m];
            float c = hc[128 + m];
            float cn = sigf(fv) * c + sigf(iv) * tanh_ex(gv);
            float hn = sigf(ov) * tanh_ex(cn);
            hc[128 + m] = cn;
            hc[m] = hn;
            out[((size_t)b * TT + t) * HH + m] = hn;
        }
        __syncthreads();
    }
}

// ---------------- launch ----------------
extern "C" void kernel_launch(void* const* d_in, const int* in_sizes, int n_in,
                              void* d_out, int out_size) {
    const float* din = (const float*)d_in[0];
    const float* Wih = (const float*)d_in[1];
    const float* Whh = (const float*)d_in[2];
    const float* bih = (const float*)d_in[3];
    const float* bhh = (const float*)d_in[4];
    const float* W1  = (const float*)d_in[5];
    const float* b1  = (const float*)d_in[6];
    const float* W2  = (const float*)d_in[7];
    const float* b2  = (const float*)d_in[8];
    const float* W3  = (const float*)d_in[9];
    const float* b3  = (const float*)d_in[10];
    float* out = (float*)d_out;

    cudaFuncSetAttribute(fused_kernel, cudaFuncAttributeMaxDynamicSharedMemorySize, SM_TOTAL);
    fused_kernel<<<NBLK, 512, SM_TOTAL>>>(din, Wih, Whh, bih, bhh, W1, b1, W2, b2, W3, b3, out);
}